// round 2
// baseline (speedup 1.0000x reference)
#include <cuda_runtime.h>
#include <cuda_bf16.h>
#include <math.h>

#define BATCH  2
#define SEQ    4096
#define DMODEL 512
#define HEADS  8
#define DHEAD  64
#define MTOT   (BATCH*SEQ)   // 8192

// Scratch buffers (allocation-free: __device__ globals)
__device__ float g_q[BATCH*SEQ*DMODEL];
__device__ float g_k[BATCH*SEQ*DMODEL];
__device__ float g_v[BATCH*SEQ*DMODEL];
__device__ float g_r[BATCH*SEQ*DMODEL];

// ---------------------------------------------------------------------------
// NT GEMM: C[m,n] = gamma[n] * (sum_k A[m,k]*W[n,k] + bias[n])
// A: [M,K] row-major, W: [N,K] row-major (torch Linear weight), both
// K-contiguous -> fully coalesced loads.
// 64x64 tile, BK=32, 256 threads, 4x4 per thread with strided ownership
// (r = ty+16i, c = tx+16j) so LDS.128 reads hit distinct bank groups
// (stride 36 floats, 36/4=9 odd).
// ---------------------------------------------------------------------------
#define GBM 64
#define GBN 64
#define GBK 32

__global__ __launch_bounds__(256) void gemm_nt_kernel(
    const float* __restrict__ A, const float* __restrict__ W,
    const float* __restrict__ gamma, const float* __restrict__ bias,
    float* __restrict__ C, int M, int Nn, int K)
{
    __shared__ float As[GBM][GBK + 4];
    __shared__ float Ws[GBN][GBK + 4];

    const int tid = threadIdx.x;
    const int tx = tid & 15;
    const int ty = tid >> 4;
    const int m0 = blockIdx.y * GBM;
    const int n0 = blockIdx.x * GBN;

    float acc[4][4];
#pragma unroll
    for (int i = 0; i < 4; i++)
#pragma unroll
        for (int j = 0; j < 4; j++) acc[i][j] = 0.f;

    for (int k0 = 0; k0 < K; k0 += GBK) {
        // 512 float4 loads per tile pair, 2 per thread per array
#pragma unroll
        for (int t = tid; t < GBM * (GBK / 4); t += 256) {
            int row = t >> 3;
            int kk  = (t & 7) << 2;
            *(float4*)&As[row][kk] =
                *(const float4*)&A[(size_t)(m0 + row) * K + k0 + kk];
            *(float4*)&Ws[row][kk] =
                *(const float4*)&W[(size_t)(n0 + row) * K + k0 + kk];
        }
        __syncthreads();

#pragma unroll
        for (int kk = 0; kk < GBK; kk += 4) {
            float4 a[4], b[4];
#pragma unroll
            for (int i = 0; i < 4; i++) a[i] = *(const float4*)&As[ty + 16 * i][kk];
#pragma unroll
            for (int j = 0; j < 4; j++) b[j] = *(const float4*)&Ws[tx + 16 * j][kk];
#pragma unroll
            for (int i = 0; i < 4; i++)
#pragma unroll
                for (int j = 0; j < 4; j++) {
                    acc[i][j] += a[i].x * b[j].x;
                    acc[i][j] += a[i].y * b[j].y;
                    acc[i][j] += a[i].z * b[j].z;
                    acc[i][j] += a[i].w * b[j].w;
                }
        }
        __syncthreads();
    }

#pragma unroll
    for (int i = 0; i < 4; i++)
#pragma unroll
        for (int j = 0; j < 4; j++) {
            int m = m0 + ty + 16 * i;
            int n = n0 + tx + 16 * j;
            float v = acc[i][j];
            if (bias) v += bias[n];
            C[(size_t)m * Nn + n] = gamma[n] * v;
        }
}

// ---------------------------------------------------------------------------
// Flash attention: one block per (b, h, 64-query tile).
// Online softmax over 64-key tiles. All fp32.
// smem: Qs/Ks/Vs/Ps each [64][68] -> 69632 B dynamic.
// ---------------------------------------------------------------------------
#define TQ 64
#define TK 64
#define SPAD 68   // 68/4 = 17 odd -> conflict-free float4 rows

__global__ __launch_bounds__(256) void attn_kernel(
    const float* __restrict__ qg, const float* __restrict__ kg,
    const float* __restrict__ vg, float* __restrict__ rg)
{
    extern __shared__ float sm[];
    float (*Qs)[SPAD] = (float(*)[SPAD])(sm);
    float (*Ks)[SPAD] = (float(*)[SPAD])(sm + TQ * SPAD);
    float (*Vs)[SPAD] = (float(*)[SPAD])(sm + 2 * TQ * SPAD);
    float (*Ps)[SPAD] = (float(*)[SPAD])(sm + 3 * TQ * SPAD);

    const int tid = threadIdx.x;
    const int tx = tid & 15;
    const int ty = tid >> 4;
    const int b  = blockIdx.z;
    const int h  = blockIdx.y;
    const int q0 = blockIdx.x * TQ;

    const float* qp = qg + (size_t)b * SEQ * DMODEL + h * DHEAD;
    const float* kp = kg + (size_t)b * SEQ * DMODEL + h * DHEAD;
    const float* vp = vg + (size_t)b * SEQ * DMODEL + h * DHEAD;

    // load Q tile once
#pragma unroll
    for (int t = tid; t < TQ * 16; t += 256) {
        int row = t >> 4;
        int d   = (t & 15) << 2;
        *(float4*)&Qs[row][d] =
            *(const float4*)&qp[(size_t)(q0 + row) * DMODEL + d];
    }

    float o[4][4];
    float mrow[4], lrow[4];
#pragma unroll
    for (int i = 0; i < 4; i++) {
        mrow[i] = -1e30f;
        lrow[i] = 0.f;
#pragma unroll
        for (int j = 0; j < 4; j++) o[i][j] = 0.f;
    }

    for (int k0 = 0; k0 < SEQ; k0 += TK) {
        // load K and V tiles
#pragma unroll
        for (int t = tid; t < TK * 16; t += 256) {
            int row = t >> 4;
            int d   = (t & 15) << 2;
            *(float4*)&Ks[row][d] =
                *(const float4*)&kp[(size_t)(k0 + row) * DMODEL + d];
            *(float4*)&Vs[row][d] =
                *(const float4*)&vp[(size_t)(k0 + row) * DMODEL + d];
        }
        __syncthreads();

        // S = scale * Q K^T (4x4 per thread, strided ownership)
        float s[4][4];
#pragma unroll
        for (int i = 0; i < 4; i++)
#pragma unroll
            for (int j = 0; j < 4; j++) s[i][j] = 0.f;

#pragma unroll
        for (int d = 0; d < DHEAD; d += 4) {
            float4 qf[4], kf[4];
#pragma unroll
            for (int i = 0; i < 4; i++) qf[i] = *(const float4*)&Qs[ty + 16 * i][d];
#pragma unroll
            for (int j = 0; j < 4; j++) kf[j] = *(const float4*)&Ks[tx + 16 * j][d];
#pragma unroll
            for (int i = 0; i < 4; i++)
#pragma unroll
                for (int j = 0; j < 4; j++) {
                    s[i][j] += qf[i].x * kf[j].x;
                    s[i][j] += qf[i].y * kf[j].y;
                    s[i][j] += qf[i].z * kf[j].z;
                    s[i][j] += qf[i].w * kf[j].w;
                }
        }

        const float SC = 0.125f;  // 1/sqrt(64)
        // online softmax, per owned row group (ty owns rows ty+16i).
        // reduction across the 16 tx lanes stays inside a 16-lane half-warp.
#pragma unroll
        for (int i = 0; i < 4; i++) {
            float tm = -1e30f;
#pragma unroll
            for (int j = 0; j < 4; j++) {
                s[i][j] *= SC;
                tm = fmaxf(tm, s[i][j]);
            }
            tm = fmaxf(tm, __shfl_xor_sync(0xffffffffu, tm, 1));
            tm = fmaxf(tm, __shfl_xor_sync(0xffffffffu, tm, 2));
            tm = fmaxf(tm, __shfl_xor_sync(0xffffffffu, tm, 4));
            tm = fmaxf(tm, __shfl_xor_sync(0xffffffffu, tm, 8));

            float mn    = fmaxf(mrow[i], tm);
            float alpha = __expf(mrow[i] - mn);
            mrow[i]     = mn;

            float rs = 0.f;
#pragma unroll
            for (int j = 0; j < 4; j++) {
                float p = __expf(s[i][j] - mn);
                s[i][j] = p;
                rs += p;
            }
            rs += __shfl_xor_sync(0xffffffffu, rs, 1);
            rs += __shfl_xor_sync(0xffffffffu, rs, 2);
            rs += __shfl_xor_sync(0xffffffffu, rs, 4);
            rs += __shfl_xor_sync(0xffffffffu, rs, 8);

            lrow[i] = lrow[i] * alpha + rs;
#pragma unroll
            for (int j = 0; j < 4; j++) o[i][j] *= alpha;
        }

        // publish P
#pragma unroll
        for (int i = 0; i < 4; i++)
#pragma unroll
            for (int j = 0; j < 4; j++)
                Ps[ty + 16 * i][tx + 16 * j] = s[i][j];
        __syncthreads();

        // O += P @ V (P rows float4-vectorized over j; V broadcast loads)
#pragma unroll
        for (int jb = 0; jb < TK; jb += 4) {
            float4 p0 = *(const float4*)&Ps[ty][jb];
            float4 p1 = *(const float4*)&Ps[ty + 16][jb];
            float4 p2 = *(const float4*)&Ps[ty + 32][jb];
            float4 p3 = *(const float4*)&Ps[ty + 48][jb];

#define PV_STEP(COMP, TT)                                                    \
            {                                                                \
                float a0 = Vs[jb + TT][tx];                                  \
                float a1 = Vs[jb + TT][tx + 16];                             \
                float a2 = Vs[jb + TT][tx + 32];                             \
                float a3 = Vs[jb + TT][tx + 48];                             \
                o[0][0] += p0.COMP * a0; o[0][1] += p0.COMP * a1;            \
                o[0][2] += p0.COMP * a2; o[0][3] += p0.COMP * a3;            \
                o[1][0] += p1.COMP * a0; o[1][1] += p1.COMP * a1;            \
                o[1][2] += p1.COMP * a2; o[1][3] += p1.COMP * a3;            \
                o[2][0] += p2.COMP * a0; o[2][1] += p2.COMP * a1;            \
                o[2][2] += p2.COMP * a2; o[2][3] += p2.COMP * a3;            \
                o[3][0] += p3.COMP * a0; o[3][1] += p3.COMP * a1;            \
                o[3][2] += p3.COMP * a2; o[3][3] += p3.COMP * a3;            \
            }
            PV_STEP(x, 0)
            PV_STEP(y, 1)
            PV_STEP(z, 2)
            PV_STEP(w, 3)
#undef PV_STEP
        }
        __syncthreads();
    }

    // epilogue: normalize and write to r in [B, N, H*Dh] layout
    float* rp = rg + (size_t)b * SEQ * DMODEL + h * DHEAD;
#pragma unroll
    for (int i = 0; i < 4; i++) {
        float inv = 1.f / lrow[i];
#pragma unroll
        for (int j = 0; j < 4; j++)
            rp[(size_t)(q0 + ty + 16 * i) * DMODEL + tx + 16 * j] = o[i][j] * inv;
    }
}

// ---------------------------------------------------------------------------
extern "C" void kernel_launch(void* const* d_in, const int* in_sizes, int n_in,
                              void* d_out, int out_size)
{
    const float* x  = (const float*)d_in[0];
    const float* Wq = (const float*)d_in[1];
    const float* Wk = (const float*)d_in[2];
    const float* Wv = (const float*)d_in[3];
    const float* Wo = (const float*)d_in[4];
    const float* bo = (const float*)d_in[5];
    const float* gq = (const float*)d_in[6];
    const float* gk = (const float*)d_in[7];
    const float* gv = (const float*)d_in[8];
    const float* go = (const float*)d_in[9];
    float* out = (float*)d_out;

    float *q, *k, *v, *r;
    cudaGetSymbolAddress((void**)&q, g_q);
    cudaGetSymbolAddress((void**)&k, g_k);
    cudaGetSymbolAddress((void**)&v, g_v);
    cudaGetSymbolAddress((void**)&r, g_r);

    dim3 gemm_grid(DMODEL / GBN, MTOT / GBM);

    // gamma-scaled projections
    gemm_nt_kernel<<<gemm_grid, 256>>>(x, Wq, gq, nullptr, q, MTOT, DMODEL, DMODEL);
    gemm_nt_kernel<<<gemm_grid, 256>>>(x, Wk, gk, nullptr, k, MTOT, DMODEL, DMODEL);
    gemm_nt_kernel<<<gemm_grid, 256>>>(x, Wv, gv, nullptr, v, MTOT, DMODEL, DMODEL);

    // flash attention
    int smem = 4 * TQ * SPAD * sizeof(float);  // 69632 B
    cudaFuncSetAttribute(attn_kernel,
                         cudaFuncAttributeMaxDynamicSharedMemorySize, smem);
    attn_kernel<<<dim3(SEQ / TQ, HEADS, BATCH), 256, smem>>>(q, k, v, r);

    // output projection with bias + gamma_out
    gemm_nt_kernel<<<gemm_grid, 256>>>(r, Wo, go, bo, out, MTOT, DMODEL, DMODEL);
}

// round 3
// speedup vs baseline: 3.0529x; 3.0529x over previous
#include <cuda_runtime.h>
#include <cuda_bf16.h>
#include <math.h>

#define BATCH  2
#define SEQ    4096
#define DMODEL 512
#define HEADS  8
#define DHEAD  64
#define MTOT   (BATCH*SEQ)   // 8192

// Scratch buffers (allocation-free: __device__ globals)
__device__ float g_q[BATCH*SEQ*DMODEL];
__device__ float g_k[BATCH*SEQ*DMODEL];
__device__ float g_v[BATCH*SEQ*DMODEL];
__device__ float g_r[BATCH*SEQ*DMODEL];

// ---------------------------------------------------------------------------
// helpers
// ---------------------------------------------------------------------------
__device__ __forceinline__ unsigned f2tf(float x) {
    unsigned u;
    asm("cvt.rna.tf32.f32 %0, %1;" : "=r"(u) : "f"(x));
    return u;
}

// mma.sync m16n8k8 tf32: C += A * B
__device__ __forceinline__ void mma_tf32(float* c, const unsigned* a,
                                         unsigned b0, unsigned b1) {
    asm volatile(
        "mma.sync.aligned.m16n8k8.row.col.f32.tf32.tf32.f32 "
        "{%0,%1,%2,%3}, {%4,%5,%6,%7}, {%8,%9}, {%0,%1,%2,%3};"
        : "+f"(c[0]), "+f"(c[1]), "+f"(c[2]), "+f"(c[3])
        : "r"(a[0]), "r"(a[1]), "r"(a[2]), "r"(a[3]), "r"(b0), "r"(b1));
}

// ---------------------------------------------------------------------------
// TF32 NT GEMM: C[m,n] = gamma[n] * (sum_k A[m,k]*W[n,k] + bias[n])
// Block 128x128xBK32, 256 threads = 8 warps (2 x 4), warp tile 64x32.
// smem stride 36 (== 4 mod 32): fragment lane pattern (8 rows x 4 cols)
// hits 32 distinct banks.
// ---------------------------------------------------------------------------
#define GBM 128
#define GBN 128
#define GBK 32
#define GST 36

__global__ __launch_bounds__(256) void gemm_tf32_kernel(
    const float* __restrict__ A, const float* __restrict__ W,
    const float* __restrict__ gamma, const float* __restrict__ bias,
    float* __restrict__ C, int M, int Nn, int K)
{
    __shared__ unsigned As[GBM * GST];
    __shared__ unsigned Ws[GBN * GST];

    const int tid   = threadIdx.x;
    const int lane  = tid & 31;
    const int warp  = tid >> 5;
    const int warpM = warp >> 2;      // 0..1  -> 64 rows
    const int warpN = warp & 3;       // 0..3  -> 32 cols
    const int g     = lane >> 2;      // group id (0..7)
    const int t4    = lane & 3;       // thread in group (0..3)
    const int m0    = blockIdx.y * GBM;
    const int n0    = blockIdx.x * GBN;

    float acc[4][4][4];               // [m-atom][n-atom][c-frag]
#pragma unroll
    for (int mi = 0; mi < 4; mi++)
#pragma unroll
        for (int ni = 0; ni < 4; ni++)
#pragma unroll
            for (int cc = 0; cc < 4; cc++) acc[mi][ni][cc] = 0.f;

    for (int k0 = 0; k0 < K; k0 += GBK) {
        // stage A and W tiles (convert to tf32)
#pragma unroll
        for (int t = tid; t < GBM * (GBK / 4); t += 256) {
            int row = t >> 3;
            int kk  = (t & 7) << 2;
            float4 fa = *(const float4*)&A[(size_t)(m0 + row) * K + k0 + kk];
            float4 fw = *(const float4*)&W[(size_t)(n0 + row) * K + k0 + kk];
            unsigned* pa = &As[row * GST + kk];
            unsigned* pw = &Ws[row * GST + kk];
            pa[0] = f2tf(fa.x); pa[1] = f2tf(fa.y); pa[2] = f2tf(fa.z); pa[3] = f2tf(fa.w);
            pw[0] = f2tf(fw.x); pw[1] = f2tf(fw.y); pw[2] = f2tf(fw.z); pw[3] = f2tf(fw.w);
        }
        __syncthreads();

#pragma unroll
        for (int ks = 0; ks < GBK / 8; ks++) {
            int kb = ks * 8 + t4;
            unsigned af[4][4];
            int ar = warpM * 64 + g;
#pragma unroll
            for (int mi = 0; mi < 4; mi++) {
                int r = ar + mi * 16;
                af[mi][0] = As[r * GST + kb];
                af[mi][1] = As[(r + 8) * GST + kb];
                af[mi][2] = As[r * GST + kb + 4];
                af[mi][3] = As[(r + 8) * GST + kb + 4];
            }
#pragma unroll
            for (int ni = 0; ni < 4; ni++) {
                int n = warpN * 32 + ni * 8 + g;
                unsigned b0 = Ws[n * GST + kb];
                unsigned b1 = Ws[n * GST + kb + 4];
#pragma unroll
                for (int mi = 0; mi < 4; mi++)
                    mma_tf32(acc[mi][ni], af[mi], b0, b1);
            }
        }
        __syncthreads();
    }

    // epilogue: gamma * (acc + bias)
#pragma unroll
    for (int mi = 0; mi < 4; mi++) {
        int r0 = m0 + warpM * 64 + mi * 16 + g;
#pragma unroll
        for (int ni = 0; ni < 4; ni++) {
            int col = n0 + warpN * 32 + ni * 8 + t4 * 2;
            float ga0 = gamma[col], ga1 = gamma[col + 1];
            float bb0 = bias ? bias[col] : 0.f;
            float bb1 = bias ? bias[col + 1] : 0.f;
            float2 v0, v1;
            v0.x = ga0 * (acc[mi][ni][0] + bb0);
            v0.y = ga1 * (acc[mi][ni][1] + bb1);
            v1.x = ga0 * (acc[mi][ni][2] + bb0);
            v1.y = ga1 * (acc[mi][ni][3] + bb1);
            *(float2*)&C[(size_t)r0 * Nn + col]       = v0;
            *(float2*)&C[(size_t)(r0 + 8) * Nn + col] = v1;
        }
    }
}

// ---------------------------------------------------------------------------
// TF32 flash attention: block = (b, h, 64-query tile), 128 threads = 4 warps,
// each warp owns 16 query rows (full 64-key width -> softmax rows stay inside
// a 4-lane shfl group). S and O live in mma C-fragments; P round-trips
// through smem to re-shape C-frag -> A-frag.
// smem strides: 68 (== 4 mod 32) for Q/K/P, 72 (== 8 mod 32) for V.
// ---------------------------------------------------------------------------
#define ATQ 64
#define QST 68
#define KST 68
#define VST 72
#define PST 68
#define ATT_SMEM ((ATQ*QST + ATQ*KST + ATQ*VST + ATQ*PST) * 4)  // 70656 B

__global__ __launch_bounds__(128) void attn_tc_kernel(
    const float* __restrict__ qg, const float* __restrict__ kg,
    const float* __restrict__ vg, float* __restrict__ rg)
{
    extern __shared__ unsigned sm[];
    unsigned* Qs = sm;
    unsigned* Ks = Qs + ATQ * QST;
    unsigned* Vs = Ks + ATQ * KST;
    unsigned* Ps = Vs + ATQ * VST;

    const int tid  = threadIdx.x;
    const int lane = tid & 31;
    const int warp = tid >> 5;
    const int g    = lane >> 2;
    const int t4   = lane & 3;
    const int b    = blockIdx.z;
    const int h    = blockIdx.y;
    const int q0   = blockIdx.x * ATQ;

    const float* qp = qg + (size_t)b * SEQ * DMODEL + h * DHEAD;
    const float* kp = kg + (size_t)b * SEQ * DMODEL + h * DHEAD;
    const float* vp = vg + (size_t)b * SEQ * DMODEL + h * DHEAD;

    // stage Q once, scale folded in (1/sqrt(64) = 0.125)
#pragma unroll
    for (int t = tid; t < ATQ * 16; t += 128) {
        int row = t >> 4;
        int d   = (t & 15) << 2;
        float4 f = *(const float4*)&qp[(size_t)(q0 + row) * DMODEL + d];
        unsigned* p = &Qs[row * QST + d];
        p[0] = f2tf(0.125f * f.x); p[1] = f2tf(0.125f * f.y);
        p[2] = f2tf(0.125f * f.z); p[3] = f2tf(0.125f * f.w);
    }

    // O accumulators: 8 n-atoms x 4 c-frags; two softmax rows per thread
    float o[8][4];
#pragma unroll
    for (int na = 0; na < 8; na++)
#pragma unroll
        for (int cc = 0; cc < 4; cc++) o[na][cc] = 0.f;
    float m0 = -1e30f, m1 = -1e30f, l0 = 0.f, l1 = 0.f;

    const int qr = warp * 16 + g;   // C-frag row 0 (row 1 = qr+8)

    for (int k0 = 0; k0 < SEQ; k0 += ATQ) {
        __syncthreads();  // previous tile's Vs reads done
#pragma unroll
        for (int t = tid; t < ATQ * 16; t += 128) {
            int row = t >> 4;
            int d   = (t & 15) << 2;
            float4 fk = *(const float4*)&kp[(size_t)(k0 + row) * DMODEL + d];
            float4 fv = *(const float4*)&vp[(size_t)(k0 + row) * DMODEL + d];
            unsigned* pk = &Ks[row * KST + d];
            unsigned* pv = &Vs[row * VST + d];
            pk[0] = f2tf(fk.x); pk[1] = f2tf(fk.y); pk[2] = f2tf(fk.z); pk[3] = f2tf(fk.w);
            pv[0] = f2tf(fv.x); pv[1] = f2tf(fv.y); pv[2] = f2tf(fv.z); pv[3] = f2tf(fv.w);
        }
        __syncthreads();

        // S = (Q*scale) K^T : warp tile 16 x 64
        float sc[8][4];
#pragma unroll
        for (int na = 0; na < 8; na++)
#pragma unroll
            for (int cc = 0; cc < 4; cc++) sc[na][cc] = 0.f;

#pragma unroll
        for (int ks = 0; ks < 8; ks++) {
            int d = ks * 8 + t4;
            unsigned qa[4];
            qa[0] = Qs[qr * QST + d];
            qa[1] = Qs[(qr + 8) * QST + d];
            qa[2] = Qs[qr * QST + d + 4];
            qa[3] = Qs[(qr + 8) * QST + d + 4];
#pragma unroll
            for (int na = 0; na < 8; na++) {
                int jn = na * 8 + g;
                unsigned b0 = Ks[jn * KST + d];
                unsigned b1 = Ks[jn * KST + d + 4];
                mma_tf32(sc[na], qa, b0, b1);
            }
        }

        // online softmax on the two C-frag rows (qr: c0/c1, qr+8: c2/c3)
        float tm0 = -1e30f, tm1 = -1e30f;
#pragma unroll
        for (int na = 0; na < 8; na++) {
            tm0 = fmaxf(tm0, fmaxf(sc[na][0], sc[na][1]));
            tm1 = fmaxf(tm1, fmaxf(sc[na][2], sc[na][3]));
        }
        tm0 = fmaxf(tm0, __shfl_xor_sync(0xffffffffu, tm0, 1));
        tm0 = fmaxf(tm0, __shfl_xor_sync(0xffffffffu, tm0, 2));
        tm1 = fmaxf(tm1, __shfl_xor_sync(0xffffffffu, tm1, 1));
        tm1 = fmaxf(tm1, __shfl_xor_sync(0xffffffffu, tm1, 2));

        float mn0 = fmaxf(m0, tm0), mn1 = fmaxf(m1, tm1);
        float a0  = __expf(m0 - mn0), a1 = __expf(m1 - mn1);
        m0 = mn0; m1 = mn1;

        float rs0 = 0.f, rs1 = 0.f;
#pragma unroll
        for (int na = 0; na < 8; na++) {
            sc[na][0] = __expf(sc[na][0] - mn0);
            sc[na][1] = __expf(sc[na][1] - mn0);
            sc[na][2] = __expf(sc[na][2] - mn1);
            sc[na][3] = __expf(sc[na][3] - mn1);
            rs0 += sc[na][0] + sc[na][1];
            rs1 += sc[na][2] + sc[na][3];
        }
        rs0 += __shfl_xor_sync(0xffffffffu, rs0, 1);
        rs0 += __shfl_xor_sync(0xffffffffu, rs0, 2);
        rs1 += __shfl_xor_sync(0xffffffffu, rs1, 1);
        rs1 += __shfl_xor_sync(0xffffffffu, rs1, 2);
        l0 = l0 * a0 + rs0;
        l1 = l1 * a1 + rs1;
#pragma unroll
        for (int na = 0; na < 8; na++) {
            o[na][0] *= a0; o[na][1] *= a0;
            o[na][2] *= a1; o[na][3] *= a1;
        }

        // publish P (per-warp private rows -> __syncwarp is enough)
#pragma unroll
        for (int na = 0; na < 8; na++) {
            int col = na * 8 + t4 * 2;
            Ps[qr * PST + col]           = f2tf(sc[na][0]);
            Ps[qr * PST + col + 1]       = f2tf(sc[na][1]);
            Ps[(qr + 8) * PST + col]     = f2tf(sc[na][2]);
            Ps[(qr + 8) * PST + col + 1] = f2tf(sc[na][3]);
        }
        __syncwarp();

        // O += P @ V
#pragma unroll
        for (int ks = 0; ks < 8; ks++) {
            int jb = ks * 8;
            unsigned pa[4];
            pa[0] = Ps[(warp * 16 + g) * PST + jb + t4];
            pa[1] = Ps[(warp * 16 + g + 8) * PST + jb + t4];
            pa[2] = Ps[(warp * 16 + g) * PST + jb + t4 + 4];
            pa[3] = Ps[(warp * 16 + g + 8) * PST + jb + t4 + 4];
#pragma unroll
            for (int na = 0; na < 8; na++) {
                int dd = na * 8 + g;
                unsigned b0 = Vs[(jb + t4) * VST + dd];
                unsigned b1 = Vs[(jb + t4 + 4) * VST + dd];
                mma_tf32(o[na], pa, b0, b1);
            }
        }
        __syncwarp();
    }

    // epilogue: normalize, write r in [B, N, H*Dh]
    float inv0 = 1.f / l0, inv1 = 1.f / l1;
    float* rp = rg + (size_t)b * SEQ * DMODEL;
#pragma unroll
    for (int na = 0; na < 8; na++) {
        int col = h * DHEAD + na * 8 + t4 * 2;
        float2 v0, v1;
        v0.x = o[na][0] * inv0; v0.y = o[na][1] * inv0;
        v1.x = o[na][2] * inv1; v1.y = o[na][3] * inv1;
        *(float2*)&rp[(size_t)(q0 + qr) * DMODEL + col]     = v0;
        *(float2*)&rp[(size_t)(q0 + qr + 8) * DMODEL + col] = v1;
    }
}

// ---------------------------------------------------------------------------
extern "C" void kernel_launch(void* const* d_in, const int* in_sizes, int n_in,
                              void* d_out, int out_size)
{
    const float* x  = (const float*)d_in[0];
    const float* Wq = (const float*)d_in[1];
    const float* Wk = (const float*)d_in[2];
    const float* Wv = (const float*)d_in[3];
    const float* Wo = (const float*)d_in[4];
    const float* bo = (const float*)d_in[5];
    const float* gq = (const float*)d_in[6];
    const float* gk = (const float*)d_in[7];
    const float* gv = (const float*)d_in[8];
    const float* go = (const float*)d_in[9];
    float* out = (float*)d_out;

    float *q, *k, *v, *r;
    cudaGetSymbolAddress((void**)&q, g_q);
    cudaGetSymbolAddress((void**)&k, g_k);
    cudaGetSymbolAddress((void**)&v, g_v);
    cudaGetSymbolAddress((void**)&r, g_r);

    dim3 gemm_grid(DMODEL / GBN, MTOT / GBM);

    gemm_tf32_kernel<<<gemm_grid, 256>>>(x, Wq, gq, nullptr, q, MTOT, DMODEL, DMODEL);
    gemm_tf32_kernel<<<gemm_grid, 256>>>(x, Wk, gk, nullptr, k, MTOT, DMODEL, DMODEL);
    gemm_tf32_kernel<<<gemm_grid, 256>>>(x, Wv, gv, nullptr, v, MTOT, DMODEL, DMODEL);

    cudaFuncSetAttribute(attn_tc_kernel,
                         cudaFuncAttributeMaxDynamicSharedMemorySize, ATT_SMEM);
    attn_tc_kernel<<<dim3(SEQ / ATQ, HEADS, BATCH), 128, ATT_SMEM>>>(q, k, v, r);

    gemm_tf32_kernel<<<gemm_grid, 256>>>(r, Wo, go, bo, out, MTOT, DMODEL, DMODEL);
}

// round 5
// speedup vs baseline: 3.3110x; 1.0845x over previous
#include <cuda_runtime.h>
#include <cuda_bf16.h>
#include <math.h>

#define BATCH  2
#define SEQ    4096
#define DMODEL 512
#define HEADS  8
#define DHEAD  64
#define MTOT   (BATCH*SEQ)   // 8192

// Scratch buffers (allocation-free: __device__ globals)
__device__ float g_q[BATCH*SEQ*DMODEL];
__device__ float g_k[BATCH*SEQ*DMODEL];
__device__ float g_v[BATCH*SEQ*DMODEL];
__device__ float g_r[BATCH*SEQ*DMODEL];

// ---------------------------------------------------------------------------
// helpers
// ---------------------------------------------------------------------------
__device__ __forceinline__ unsigned f2tf(float x) {
    unsigned u;
    asm("cvt.rna.tf32.f32 %0, %1;" : "=r"(u) : "f"(x));
    return u;
}

// mma.sync m16n8k8 tf32: C += A * B
__device__ __forceinline__ void mma_tf32(float* c, const unsigned* a,
                                         unsigned b0, unsigned b1) {
    asm volatile(
        "mma.sync.aligned.m16n8k8.row.col.f32.tf32.tf32.f32 "
        "{%0,%1,%2,%3}, {%4,%5,%6,%7}, {%8,%9}, {%0,%1,%2,%3};"
        : "+f"(c[0]), "+f"(c[1]), "+f"(c[2]), "+f"(c[3])
        : "r"(a[0]), "r"(a[1]), "r"(a[2]), "r"(a[3]), "r"(b0), "r"(b1));
}

// ---------------------------------------------------------------------------
// TF32 NT GEMM: C[m,n] = gamma[n] * (sum_k A[m,k]*W[n,k] + bias[n])
// Block 128x128xBK32, 256 threads = 8 warps (2 x 4), warp tile 64x32.
// smem stride 36 (== 4 mod 32): fragment lane pattern (8 rows x 4 cols)
// hits 32 distinct banks.
// ---------------------------------------------------------------------------
#define GBM 128
#define GBN 128
#define GBK 32
#define GST 36

__global__ __launch_bounds__(256) void gemm_tf32_kernel(
    const float* __restrict__ A, const float* __restrict__ W,
    const float* __restrict__ gamma, const float* __restrict__ bias,
    float* __restrict__ C, int M, int Nn, int K)
{
    __shared__ unsigned As[GBM * GST];
    __shared__ unsigned Ws[GBN * GST];

    const int tid   = threadIdx.x;
    const int lane  = tid & 31;
    const int warp  = tid >> 5;
    const int warpM = warp >> 2;      // 0..1  -> 64 rows
    const int warpN = warp & 3;       // 0..3  -> 32 cols
    const int g     = lane >> 2;      // group id (0..7)
    const int t4    = lane & 3;       // thread in group (0..3)
    const int m0    = blockIdx.y * GBM;
    const int n0    = blockIdx.x * GBN;

    float acc[4][4][4];               // [m-atom][n-atom][c-frag]
#pragma unroll
    for (int mi = 0; mi < 4; mi++)
#pragma unroll
        for (int ni = 0; ni < 4; ni++)
#pragma unroll
            for (int cc = 0; cc < 4; cc++) acc[mi][ni][cc] = 0.f;

    for (int k0 = 0; k0 < K; k0 += GBK) {
        // stage A and W tiles (convert to tf32)
#pragma unroll
        for (int t = tid; t < GBM * (GBK / 4); t += 256) {
            int row = t >> 3;
            int kk  = (t & 7) << 2;
            float4 fa = *(const float4*)&A[(size_t)(m0 + row) * K + k0 + kk];
            float4 fw = *(const float4*)&W[(size_t)(n0 + row) * K + k0 + kk];
            unsigned* pa = &As[row * GST + kk];
            unsigned* pw = &Ws[row * GST + kk];
            pa[0] = f2tf(fa.x); pa[1] = f2tf(fa.y); pa[2] = f2tf(fa.z); pa[3] = f2tf(fa.w);
            pw[0] = f2tf(fw.x); pw[1] = f2tf(fw.y); pw[2] = f2tf(fw.z); pw[3] = f2tf(fw.w);
        }
        __syncthreads();

#pragma unroll
        for (int ks = 0; ks < GBK / 8; ks++) {
            int kb = ks * 8 + t4;
            unsigned af[4][4];
            int ar = warpM * 64 + g;
#pragma unroll
            for (int mi = 0; mi < 4; mi++) {
                int r = ar + mi * 16;
                af[mi][0] = As[r * GST + kb];
                af[mi][1] = As[(r + 8) * GST + kb];
                af[mi][2] = As[r * GST + kb + 4];
                af[mi][3] = As[(r + 8) * GST + kb + 4];
            }
#pragma unroll
            for (int ni = 0; ni < 4; ni++) {
                int n = warpN * 32 + ni * 8 + g;
                unsigned b0 = Ws[n * GST + kb];
                unsigned b1 = Ws[n * GST + kb + 4];
#pragma unroll
                for (int mi = 0; mi < 4; mi++)
                    mma_tf32(acc[mi][ni], af[mi], b0, b1);
            }
        }
        __syncthreads();
    }

    // epilogue: gamma * (acc + bias)
#pragma unroll
    for (int mi = 0; mi < 4; mi++) {
        int r0 = m0 + warpM * 64 + mi * 16 + g;
#pragma unroll
        for (int ni = 0; ni < 4; ni++) {
            int col = n0 + warpN * 32 + ni * 8 + t4 * 2;
            float ga0 = gamma[col], ga1 = gamma[col + 1];
            float bb0 = bias ? bias[col] : 0.f;
            float bb1 = bias ? bias[col + 1] : 0.f;
            float2 v0, v1;
            v0.x = ga0 * (acc[mi][ni][0] + bb0);
            v0.y = ga1 * (acc[mi][ni][1] + bb1);
            v1.x = ga0 * (acc[mi][ni][2] + bb0);
            v1.y = ga1 * (acc[mi][ni][3] + bb1);
            *(float2*)&C[(size_t)r0 * Nn + col]       = v0;
            *(float2*)&C[(size_t)(r0 + 8) * Nn + col] = v1;
        }
    }
}

// ---------------------------------------------------------------------------
// TF32 flash attention v2.
// Block = (b, h, 128-query tile), 128 threads = 4 warps.
// Warp tile: 32 q-rows x 64 keys (2 m-atoms -> K/V B-frags amortized 2x).
// Q fragments hoisted into registers once (no per-iter Q LDS).
// Q and P share one smem region (after frag hoist each warp touches only
// its own 32 rows -> no cross-warp hazard).
// smem strides: 68 (== 4 mod 32) for Q/P/K, 72 (== 8 mod 32) for V.
// ---------------------------------------------------------------------------
#define ATQ 128
#define ATK 64
#define QPST 68
#define KST 68
#define VST 72
#define ATT_SMEM ((ATQ*QPST + ATK*KST + ATK*VST) * 4)  // 70656 B

__global__ __launch_bounds__(128) void attn_tc_kernel(
    const float* __restrict__ qg, const float* __restrict__ kg,
    const float* __restrict__ vg, float* __restrict__ rg)
{
    extern __shared__ unsigned sm[];
    unsigned* QPs = sm;                   // 128 x 68 (Q, then reused for P)
    unsigned* Ks  = QPs + ATQ * QPST;     // 64 x 68
    unsigned* Vs  = Ks  + ATK * KST;      // 64 x 72

    const int tid  = threadIdx.x;
    const int lane = tid & 31;
    const int warp = tid >> 5;
    const int g    = lane >> 2;
    const int t4   = lane & 3;
    const int b    = blockIdx.z;
    const int h    = blockIdx.y;
    const int q0   = blockIdx.x * ATQ;

    const float* qp = qg + (size_t)b * SEQ * DMODEL + h * DHEAD;
    const float* kp = kg + (size_t)b * SEQ * DMODEL + h * DHEAD;
    const float* vp = vg + (size_t)b * SEQ * DMODEL + h * DHEAD;

    // stage Q once, softmax scale folded in (1/sqrt(64) = 0.125)
#pragma unroll
    for (int t = tid; t < ATQ * 16; t += 128) {
        int row = t >> 4;
        int d   = (t & 15) << 2;
        float4 f = *(const float4*)&qp[(size_t)(q0 + row) * DMODEL + d];
        unsigned* p = &QPs[row * QPST + d];
        p[0] = f2tf(0.125f * f.x); p[1] = f2tf(0.125f * f.y);
        p[2] = f2tf(0.125f * f.z); p[3] = f2tf(0.125f * f.w);
    }
    __syncthreads();

    const int r0 = warp * 32 + g;   // this thread's base C-frag row

    // hoist Q A-fragments into registers: [ks][m-atom][frag]
    unsigned qf[8][2][4];
#pragma unroll
    for (int ks = 0; ks < 8; ks++) {
        int d = ks * 8 + t4;
#pragma unroll
        for (int mi = 0; mi < 2; mi++) {
            int rr = r0 + mi * 16;
            qf[ks][mi][0] = QPs[rr * QPST + d];
            qf[ks][mi][1] = QPs[(rr + 8) * QPST + d];
            qf[ks][mi][2] = QPs[rr * QPST + d + 4];
            qf[ks][mi][3] = QPs[(rr + 8) * QPST + d + 4];
        }
    }
    // QPs region now owned per-warp (rows warp*32..warp*32+31) as P buffer.

    float o[2][8][4];
    float mx[2][2], ll[2][2];
#pragma unroll
    for (int mi = 0; mi < 2; mi++) {
        mx[mi][0] = -1e30f; mx[mi][1] = -1e30f;
        ll[mi][0] = 0.f;    ll[mi][1] = 0.f;
#pragma unroll
        for (int na = 0; na < 8; na++)
#pragma unroll
            for (int cc = 0; cc < 4; cc++) o[mi][na][cc] = 0.f;
    }

    for (int k0 = 0; k0 < SEQ; k0 += ATK) {
        __syncthreads();  // previous iter's K/V + P reads complete
#pragma unroll
        for (int t = tid; t < ATK * 16; t += 128) {
            int row = t >> 4;
            int d   = (t & 15) << 2;
            float4 fk = *(const float4*)&kp[(size_t)(k0 + row) * DMODEL + d];
            float4 fv = *(const float4*)&vp[(size_t)(k0 + row) * DMODEL + d];
            unsigned* pk = &Ks[row * KST + d];
            unsigned* pv = &Vs[row * VST + d];
            pk[0] = f2tf(fk.x); pk[1] = f2tf(fk.y); pk[2] = f2tf(fk.z); pk[3] = f2tf(fk.w);
            pv[0] = f2tf(fv.x); pv[1] = f2tf(fv.y); pv[2] = f2tf(fv.z); pv[3] = f2tf(fv.w);
        }
        __syncthreads();

        // S = (Q*scale) K^T : warp tile 32 x 64
        float sc[2][8][4];
#pragma unroll
        for (int mi = 0; mi < 2; mi++)
#pragma unroll
            for (int na = 0; na < 8; na++)
#pragma unroll
                for (int cc = 0; cc < 4; cc++) sc[mi][na][cc] = 0.f;

#pragma unroll
        for (int ks = 0; ks < 8; ks++) {
            int d = ks * 8 + t4;
#pragma unroll
            for (int na = 0; na < 8; na++) {
                int jn = na * 8 + g;
                unsigned b0 = Ks[jn * KST + d];
                unsigned b1 = Ks[jn * KST + d + 4];
                mma_tf32(sc[0][na], qf[ks][0], b0, b1);
                mma_tf32(sc[1][na], qf[ks][1], b0, b1);
            }
        }

        // online softmax: 4 row-halves per thread (mi x {c01, c23})
#pragma unroll
        for (int mi = 0; mi < 2; mi++) {
            float tm0 = -1e30f, tm1 = -1e30f;
#pragma unroll
            for (int na = 0; na < 8; na++) {
                tm0 = fmaxf(tm0, fmaxf(sc[mi][na][0], sc[mi][na][1]));
                tm1 = fmaxf(tm1, fmaxf(sc[mi][na][2], sc[mi][na][3]));
            }
            tm0 = fmaxf(tm0, __shfl_xor_sync(0xffffffffu, tm0, 1));
            tm0 = fmaxf(tm0, __shfl_xor_sync(0xffffffffu, tm0, 2));
            tm1 = fmaxf(tm1, __shfl_xor_sync(0xffffffffu, tm1, 1));
            tm1 = fmaxf(tm1, __shfl_xor_sync(0xffffffffu, tm1, 2));

            float mn0 = fmaxf(mx[mi][0], tm0), mn1 = fmaxf(mx[mi][1], tm1);
            float a0  = __expf(mx[mi][0] - mn0), a1 = __expf(mx[mi][1] - mn1);
            mx[mi][0] = mn0; mx[mi][1] = mn1;

            float rs0 = 0.f, rs1 = 0.f;
#pragma unroll
            for (int na = 0; na < 8; na++) {
                sc[mi][na][0] = __expf(sc[mi][na][0] - mn0);
                sc[mi][na][1] = __expf(sc[mi][na][1] - mn0);
                sc[mi][na][2] = __expf(sc[mi][na][2] - mn1);
                sc[mi][na][3] = __expf(sc[mi][na][3] - mn1);
                rs0 += sc[mi][na][0] + sc[mi][na][1];
                rs1 += sc[mi][na][2] + sc[mi][na][3];
            }
            rs0 += __shfl_xor_sync(0xffffffffu, rs0, 1);
            rs0 += __shfl_xor_sync(0xffffffffu, rs0, 2);
            rs1 += __shfl_xor_sync(0xffffffffu, rs1, 1);
            rs1 += __shfl_xor_sync(0xffffffffu, rs1, 2);
            ll[mi][0] = ll[mi][0] * a0 + rs0;
            ll[mi][1] = ll[mi][1] * a1 + rs1;
#pragma unroll
            for (int na = 0; na < 8; na++) {
                o[mi][na][0] *= a0; o[mi][na][1] *= a0;
                o[mi][na][2] *= a1; o[mi][na][3] *= a1;
            }
        }

        // publish P to this warp's rows of QPs
#pragma unroll
        for (int mi = 0; mi < 2; mi++) {
            int rr = r0 + mi * 16;
#pragma unroll
            for (int na = 0; na < 8; na++) {
                int col = na * 8 + t4 * 2;
                QPs[rr * QPST + col]           = f2tf(sc[mi][na][0]);
                QPs[rr * QPST + col + 1]       = f2tf(sc[mi][na][1]);
                QPs[(rr + 8) * QPST + col]     = f2tf(sc[mi][na][2]);
                QPs[(rr + 8) * QPST + col + 1] = f2tf(sc[mi][na][3]);
            }
        }
        __syncwarp();

        // O += P @ V
#pragma unroll
        for (int ks = 0; ks < 8; ks++) {
            int jb = ks * 8;
            unsigned pa[2][4];
#pragma unroll
            for (int mi = 0; mi < 2; mi++) {
                int rr = r0 + mi * 16;
                pa[mi][0] = QPs[rr * QPST + jb + t4];
                pa[mi][1] = QPs[(rr + 8) * QPST + jb + t4];
                pa[mi][2] = QPs[rr * QPST + jb + t4 + 4];
                pa[mi][3] = QPs[(rr + 8) * QPST + jb + t4 + 4];
            }
#pragma unroll
            for (int na = 0; na < 8; na++) {
                int dd = na * 8 + g;
                unsigned b0 = Vs[(jb + t4) * VST + dd];
                unsigned b1 = Vs[(jb + t4 + 4) * VST + dd];
                mma_tf32(o[0][na], pa[0], b0, b1);
                mma_tf32(o[1][na], pa[1], b0, b1);
            }
        }
    }

    // epilogue: normalize, write r in [B, N, H*Dh]
    float* rp = rg + (size_t)b * SEQ * DMODEL;
#pragma unroll
    for (int mi = 0; mi < 2; mi++) {
        float inv0 = 1.f / ll[mi][0], inv1 = 1.f / ll[mi][1];
        int rr = q0 + r0 + mi * 16;
#pragma unroll
        for (int na = 0; na < 8; na++) {
            int col = h * DHEAD + na * 8 + t4 * 2;
            float2 v0, v1;
            v0.x = o[mi][na][0] * inv0; v0.y = o[mi][na][1] * inv0;
            v1.x = o[mi][na][2] * inv1; v1.y = o[mi][na][3] * inv1;
            *(float2*)&rp[(size_t)rr * DMODEL + col]       = v0;
            *(float2*)&rp[(size_t)(rr + 8) * DMODEL + col] = v1;
        }
    }
}

// ---------------------------------------------------------------------------
extern "C" void kernel_launch(void* const* d_in, const int* in_sizes, int n_in,
                              void* d_out, int out_size)
{
    const float* x  = (const float*)d_in[0];
    const float* Wq = (const float*)d_in[1];
    const float* Wk = (const float*)d_in[2];
    const float* Wv = (const float*)d_in[3];
    const float* Wo = (const float*)d_in[4];
    const float* bo = (const float*)d_in[5];
    const float* gq = (const float*)d_in[6];
    const float* gk = (const float*)d_in[7];
    const float* gv = (const float*)d_in[8];
    const float* go = (const float*)d_in[9];
    float* out = (float*)d_out;

    float *q, *k, *v, *r;
    cudaGetSymbolAddress((void**)&q, g_q);
    cudaGetSymbolAddress((void**)&k, g_k);
    cudaGetSymbolAddress((void**)&v, g_v);
    cudaGetSymbolAddress((void**)&r, g_r);

    dim3 gemm_grid(DMODEL / GBN, MTOT / GBM);

    gemm_tf32_kernel<<<gemm_grid, 256>>>(x, Wq, gq, nullptr, q, MTOT, DMODEL, DMODEL);
    gemm_tf32_kernel<<<gemm_grid, 256>>>(x, Wk, gk, nullptr, k, MTOT, DMODEL, DMODEL);
    gemm_tf32_kernel<<<gemm_grid, 256>>>(x, Wv, gv, nullptr, v, MTOT, DMODEL, DMODEL);

    cudaFuncSetAttribute(attn_tc_kernel,
                         cudaFuncAttributeMaxDynamicSharedMemorySize, ATT_SMEM);
    attn_tc_kernel<<<dim3(SEQ / ATQ, HEADS, BATCH), 128, ATT_SMEM>>>(q, k, v, r);

    gemm_tf32_kernel<<<gemm_grid, 256>>>(r, Wo, go, bo, out, MTOT, DMODEL, DMODEL);
}